// round 7
// baseline (speedup 1.0000x reference)
#include <cuda_runtime.h>
#include <cuda_bf16.h>
#include <math.h>

#define BB 8
#define LL 2048
#define DM 512
#define DI 1024
#define DS 16
#define DTR 32
#define CC 32          // time chunks
#define TT 64          // chunk length
#define EPSV 1e-5f

typedef unsigned long long u64;

__device__ __forceinline__ u64 pk2(float lo, float hi) {
    u64 r; asm("mov.b64 %0, {%1, %2};" : "=l"(r) : "f"(lo), "f"(hi)); return r;
}
__device__ __forceinline__ void upk2(u64 v, float& a, float& b) {
    asm("mov.b64 {%0, %1}, %2;" : "=f"(a), "=f"(b) : "l"(v));
}
__device__ __forceinline__ u64 f2fma(u64 a, u64 b, u64 c) {
    u64 d; asm("fma.rn.f32x2 %0, %1, %2, %3;" : "=l"(d) : "l"(a), "l"(b), "l"(c)); return d;
}
__device__ __forceinline__ u64 f2mul(u64 a, u64 b) {
    u64 d; asm("mul.rn.f32x2 %0, %1, %2;" : "=l"(d) : "l"(a), "l"(b)); return d;
}
__device__ __forceinline__ u64 f2add(u64 a, u64 b) {
    u64 d; asm("add.rn.f32x2 %0, %1, %2;" : "=l"(d) : "l"(a), "l"(b)); return d;
}

union F4U2 { float4 f4; u64 u2[2]; };

// packed powers: p[k] = {e1^(2k+1), e1^(2k+2)}
__device__ __forceinline__ void pow16(float e1, u64* p) {
    float e2 = e1 * e1, e4 = e2 * e2, e8 = e4 * e4;
    p[0] = pk2(e1, e2);
    u64 m2 = pk2(e2, e2);
    p[1] = f2mul(p[0], m2);
    u64 m4 = pk2(e4, e4);
    p[2] = f2mul(p[0], m4);
    p[3] = f2mul(p[1], m4);
    u64 m8 = pk2(e8, e8);
    p[4] = f2mul(p[0], m8);
    p[5] = f2mul(p[1], m8);
    p[6] = f2mul(p[2], m8);
    p[7] = f2mul(p[3], m8);
}

// scalar power tree for scan2
#define POWTREE(p, e1)                                                          \
    {                                                                           \
        p[0] = (e1);  p[1] = p[0] * p[0];  p[2] = p[1] * p[0];                  \
        p[3] = p[1] * p[1];  p[4] = p[3] * p[0];  p[5] = p[3] * p[1];           \
        p[6] = p[3] * p[2];  p[7] = p[3] * p[3];  p[8] = p[7] * p[0];           \
        p[9] = p[7] * p[1];  p[10] = p[7] * p[2]; p[11] = p[7] * p[3];          \
        p[12] = p[7] * p[4]; p[13] = p[7] * p[5]; p[14] = p[7] * p[6];          \
        p[15] = p[7] * p[7];                                                    \
    }

// ---------------- scratch (device globals; no runtime allocation) -------------
__device__ float g_scal[8];                 // mw, mb, mww, mwb, mbb
__device__ int   g_fastA;
__device__ float g_p1[2 * DI];
__device__ float g_p2[2 * DI];
__device__ float g_p3[2 * DI];
__device__ float g_weff[DI];
__device__ float g_A[DI * DS];              // -exp(A_log)
__device__ float g_a[BB * LL];
__device__ float g_c[BB * LL];
__device__ float g_xc[(size_t)BB * DI * LL];   // [b][d][t] conv+silu
__device__ float g_dtl[BB * LL * DTR];         // [b][t][32] dt low-rank
__device__ float g_Bt[BB * DS * LL];           // [b][s][t]
__device__ float g_Ct[BB * DS * LL];           // [b][s][t]
__device__ float g_dtT[(size_t)BB * DI * LL];  // [b][d][t] softplus(dt)
__device__ float g_hF[(size_t)BB * CC * DI * DS];
__device__ float g_Ssum[BB * CC * DI];
__device__ float g_H[(size_t)BB * CC * DI * DS];
__device__ float g_red[4 * BB * LL];

// ---------------- K1: moments of W_in1 / b_in1 --------------------------------
__global__ void k_stats(const float* __restrict__ w, const float* __restrict__ b) {
    __shared__ float sh[5][16];
    int tid = threadIdx.x;               // 512 threads
    float wv = w[tid], bv = b[tid];
    float v[5] = {wv, bv, wv * wv, wv * bv, bv * bv};
#pragma unroll
    for (int j = 0; j < 5; j++) {
#pragma unroll
        for (int o = 16; o > 0; o >>= 1) v[j] += __shfl_xor_sync(0xffffffffu, v[j], o);
    }
    if ((tid & 31) == 0) {
#pragma unroll
        for (int j = 0; j < 5; j++) sh[j][tid >> 5] = v[j];
    }
    if (tid == 0) g_fastA = 1;
    __syncthreads();
    if (tid < 5) {
        float s = 0.f;
#pragma unroll
        for (int k = 0; k < 16; k++) s += sh[tid][k];
        g_scal[tid] = s * (1.0f / DM);
    }
}

// ---------------- K2: p-vectors (coalesced), w_eff, A, per-token a/c ----------
__global__ void k_prep(const float* __restrict__ Win1, const float* __restrict__ bin1,
                       const float* __restrict__ lng,  const float* __restrict__ lnb,
                       const float* __restrict__ Wxz,  const float* __restrict__ Wom,
                       const float* __restrict__ Wout, const float* __restrict__ Alog,
                       const float* __restrict__ x) {
    int bx = blockIdx.x;
    int tid = threadIdx.x;
    float mw = g_scal[0], mb = g_scal[1], mww = g_scal[2], mwb = g_scal[3], mbb = g_scal[4];
    if (bx < 8) {
        int col = bx * 256 + tid;
        float s1 = 0.f, s2 = 0.f, s3 = 0.f;
        for (int d = 0; d < DM; d++) {
            float gd = lng[d];
            float u = (Win1[d] - mw) * gd;
            float v = (bin1[d] - mb) * gd;
            float wv = Wxz[(size_t)d * (2 * DI) + col];
            s1 = fmaf(u, wv, s1);
            s2 = fmaf(v, wv, s2);
            s3 = fmaf(lnb[d], wv, s3);
        }
        g_p1[col] = s1; g_p2[col] = s2; g_p3[col] = s3;
    } else {
        int idx = (bx - 8) * 256 + tid;
        if (idx < DI) {
            float s = 0.f;
            for (int m = 0; m < DM; m++) s = fmaf(Wom[idx * DM + m], Wout[m], s);
            g_weff[idx] = s;
        } else if (idx < DI + DI * DS) {
            int i2 = idx - DI;
            float av = -expf(Alog[i2]);
            g_A[i2] = av;
            int s = i2 & (DS - 1);
            float expect = -(float)(s + 1);
            if (fabsf(av - expect) > 1e-4f * (float)(s + 1)) atomicAnd(&g_fastA, 0);
        } else if (idx < DI + DI * DS + BB * LL) {
            int i2 = idx - DI - DI * DS;
            float xv = x[i2];
            float varw = mww - mw * mw;
            float cwb  = mwb - mw * mb;
            float varb = mbb - mb * mb;
            float var  = fmaf(xv * xv, varw, fmaf(2.0f * xv, cwb, varb));
            float s    = rsqrtf(var + EPSV);
            g_a[i2] = xv * s;
            g_c[i2] = s;
        }
    }
}

// ---------------- K3: conv + silu -> xc ---------------------------------------
__global__ __launch_bounds__(256) void k_xc(const float* __restrict__ convw,
                                            const float* __restrict__ convb) {
    int bx = blockIdx.x;                      // 1024 blocks
    int b   = bx >> 7;
    int rem = bx & 127;
    int t0  = (rem >> 2) * 64;
    int d   = (rem & 3) * 256 + threadIdx.x;

    __shared__ float shA[67], shC[67];
    if (threadIdx.x < 67) {
        int gt = t0 - 3 + (int)threadIdx.x;
        shA[threadIdx.x] = (gt >= 0) ? g_a[b * LL + gt] : 0.f;
        shC[threadIdx.x] = (gt >= 0) ? g_c[b * LL + gt] : 0.f;
    }
    float p1d = g_p1[d], p2d = g_p2[d], p3d = g_p3[d];
    float cw0 = convw[d * 4 + 0], cw1 = convw[d * 4 + 1];
    float cw2 = convw[d * 4 + 2], cw3 = convw[d * 4 + 3];
    float cb = convb[d];
    float cwsum = cw0 + cw1 + cw2 + cw3;
    __syncthreads();

    float* xop = g_xc + ((size_t)(b * DI + d)) * LL + t0;
    float xb[8];
#pragma unroll 8
    for (int tt = 0; tt < 64; tt++) {
        int t = t0 + tt;
        float a0 = shA[tt], a1 = shA[tt + 1], a2 = shA[tt + 2], a3 = shA[tt + 3];
        float c0 = shC[tt], c1 = shC[tt + 1], c2 = shC[tt + 2], c3 = shC[tt + 3];
        float sa = fmaf(a0, cw0, fmaf(a1, cw1, fmaf(a2, cw2, a3 * cw3)));
        float sc = fmaf(c0, cw0, fmaf(c1, cw1, fmaf(c2, cw2, c3 * cw3)));
        float sw;
        if (t >= 3) sw = cwsum;
        else { sw = cw3; if (t >= 1) sw += cw2; if (t >= 2) sw += cw1; }
        float pre = fmaf(p1d, sa, fmaf(p2d, sc, fmaf(p3d, sw, cb)));
        xb[tt & 7] = __fdividef(pre, 1.0f + __expf(-pre));
        if ((tt & 7) == 7) {
            *(float4*)(xop + tt - 7) = make_float4(xb[0], xb[1], xb[2], xb[3]);
            *(float4*)(xop + tt - 3) = make_float4(xb[4], xb[5], xb[6], xb[7]);
        }
    }
}

// ---------------- K4: xc @ W_xp -> dt_low, B^T, C^T ---------------------------
__global__ __launch_bounds__(256) void k_proj(const float* __restrict__ Wxp) {
    int blk = blockIdx.x;                    // 256 blocks
    int b  = blk >> 5;
    int t0 = (blk & 31) * 64;
    __shared__ float At[32][68];
    __shared__ float Bt_[32][64];
    int tid = threadIdx.x;
    int tx = tid & 15, ty = tid >> 4;
    float acc[4][4];
#pragma unroll
    for (int i = 0; i < 4; i++)
#pragma unroll
        for (int j = 0; j < 4; j++) acc[i][j] = 0.f;

    for (int k0 = 0; k0 < DI; k0 += 32) {
#pragma unroll
        for (int i = 0; i < 2; i++) {
            int q = tid + i * 256;           // q < 512
            int kk = q >> 4, t4 = q & 15;
            float4 v = *(const float4*)(g_xc + ((size_t)(b * DI + k0 + kk)) * LL + t0 + t4 * 4);
            *(float4*)&At[kk][t4 * 4] = v;
        }
#pragma unroll
        for (int i = 0; i < 2; i++) {
            int q = tid + i * 256;           // q < 512
            int kk = q >> 4, n4 = q & 15;
            float4 v = *(const float4*)(Wxp + (size_t)(k0 + kk) * 64 + n4 * 4);
            *(float4*)&Bt_[kk][n4 * 4] = v;
        }
        __syncthreads();
#pragma unroll
        for (int kk = 0; kk < 32; kk++) {
            float4 bv = *(float4*)&Bt_[kk][tx * 4];
#pragma unroll
            for (int i = 0; i < 4; i++) {
                float av = At[kk][ty * 4 + i];
                acc[i][0] = fmaf(av, bv.x, acc[i][0]);
                acc[i][1] = fmaf(av, bv.y, acc[i][1]);
                acc[i][2] = fmaf(av, bv.z, acc[i][2]);
                acc[i][3] = fmaf(av, bv.w, acc[i][3]);
            }
        }
        __syncthreads();
    }
#pragma unroll
    for (int i = 0; i < 4; i++) {
        int t = t0 + ty * 4 + i;
        if (tx < 8) {
            *(float4*)(g_dtl + ((size_t)(b * LL + t)) * DTR + tx * 4) =
                make_float4(acc[i][0], acc[i][1], acc[i][2], acc[i][3]);
        } else {
#pragma unroll
            for (int j = 0; j < 4; j++) {
                int n = tx * 4 + j;
                if (n < 48) g_Bt[((size_t)(b * DS + n - 32)) * LL + t] = acc[i][j];
                else        g_Ct[((size_t)(b * DS + n - 48)) * LL + t] = acc[i][j];
            }
        }
    }
}

// ---------------- K5: softplus(dt_low @ W_dt + b_dt) -> dtT (packed) ----------
__global__ __launch_bounds__(256) void k_dt(const float* __restrict__ Wdt,
                                            const float* __restrict__ bdt) {
    int blk = blockIdx.x;                    // 1024 blocks
    int b   = blk >> 7;
    int rem = blk & 127;
    int t0  = (rem >> 2) * 64;
    int d   = (rem & 3) * 256 + threadIdx.x;
    __shared__ float sh[64][32];
    const float4* src = (const float4*)(g_dtl + ((size_t)(b * LL + t0)) * DTR);
    float4* dst = (float4*)&sh[0][0];
    for (int i = threadIdx.x; i < 512; i += 256) dst[i] = src[i];
    u64 w2[16];
#pragma unroll
    for (int k = 0; k < 16; k++)
        w2[k] = pk2(Wdt[(size_t)(2 * k) * DI + d], Wdt[(size_t)(2 * k + 1) * DI + d]);
    float bd = bdt[d];
    __syncthreads();
    float* op = g_dtT + ((size_t)(b * DI + d)) * LL + t0;
    float buf[8];
#pragma unroll 4
    for (int tt = 0; tt < 64; tt++) {
        const float4* vp = (const float4*)&sh[tt][0];
        F4U2 q0, q1, q2, q3, q4, q5, q6, q7;
        q0.f4 = vp[0]; q1.f4 = vp[1]; q2.f4 = vp[2]; q3.f4 = vp[3];
        q4.f4 = vp[4]; q5.f4 = vp[5]; q6.f4 = vp[6]; q7.f4 = vp[7];
        u64 ac0 = f2mul(q0.u2[0], w2[0]);
        u64 ac1 = f2mul(q0.u2[1], w2[1]);
        ac0 = f2fma(q1.u2[0], w2[2], ac0);
        ac1 = f2fma(q1.u2[1], w2[3], ac1);
        ac0 = f2fma(q2.u2[0], w2[4], ac0);
        ac1 = f2fma(q2.u2[1], w2[5], ac1);
        ac0 = f2fma(q3.u2[0], w2[6], ac0);
        ac1 = f2fma(q3.u2[1], w2[7], ac1);
        ac0 = f2fma(q4.u2[0], w2[8], ac0);
        ac1 = f2fma(q4.u2[1], w2[9], ac1);
        ac0 = f2fma(q5.u2[0], w2[10], ac0);
        ac1 = f2fma(q5.u2[1], w2[11], ac1);
        ac0 = f2fma(q6.u2[0], w2[12], ac0);
        ac1 = f2fma(q6.u2[1], w2[13], ac1);
        ac0 = f2fma(q7.u2[0], w2[14], ac0);
        ac1 = f2fma(q7.u2[1], w2[15], ac1);
        u64 acs = f2add(ac0, ac1);
        float alo, ahi;
        upk2(acs, alo, ahi);
        float acc = alo + ahi + bd;
        buf[tt & 7] = (acc > 20.0f) ? acc : log1pf(__expf(acc));
        if ((tt & 7) == 7) {
            *(float4*)(op + tt - 7) = make_float4(buf[0], buf[1], buf[2], buf[3]);
            *(float4*)(op + tt - 3) = make_float4(buf[4], buf[5], buf[6], buf[7]);
        }
    }
}

// ---------------- K6a: chunk-local scan (streamed dt/xc, packed states) -------
__global__ __launch_bounds__(256) void k_scan1(void) {
    int blk = blockIdx.x;                // 1024 = b(8) x c(32) x dg(4)
    int b  = blk >> 7;
    int c  = (blk >> 2) & 31;
    int dg = blk & 3;
    int tid = threadIdx.x;
    int d  = dg * 256 + tid;
    int t0 = c * TT;

    __shared__ float Bs[TT][DS];
    for (int i = tid; i < TT * DS; i += 256) {
        int s = i >> 6, t = i & 63;
        Bs[t][s] = g_Bt[((size_t)b * DS + s) * LL + t0 + t];
    }
    const float4* dtp = (const float4*)(g_dtT + ((size_t)b * DI + d) * LL + t0);
    const float4* xcp = (const float4*)(g_xc  + ((size_t)b * DI + d) * LL + t0);
    int fast = g_fastA;
    float Areg[16];
    if (!fast) {
#pragma unroll
        for (int s = 0; s < 16; s++) Areg[s] = g_A[d * DS + s];
    }
    __syncthreads();

    u64 h2[8];
#pragma unroll
    for (int k = 0; k < 8; k++) h2[k] = 0ULL;
    float S = 0.f;

#pragma unroll 4
    for (int q = 0; q < TT / 4; q++) {
        float4 dtv = dtp[q], xcv = xcp[q];
#pragma unroll
        for (int u = 0; u < 4; u++) {
            float dtc = (u == 0) ? dtv.x : (u == 1) ? dtv.y : (u == 2) ? dtv.z : dtv.w;
            float xcc = (u == 0) ? xcv.x : (u == 1) ? xcv.y : (u == 2) ? xcv.z : xcv.w;
            int t = q * 4 + u;
            S += dtc;
            float dx = dtc * xcc;
            u64 dx2 = pk2(dx, dx);
            u64 p2r[8];
            if (fast) {
                pow16(__expf(-dtc), p2r);
            } else {
                float ps[16];
#pragma unroll
                for (int s = 0; s < 16; s++) ps[s] = __expf(dtc * Areg[s]);
#pragma unroll
                for (int k = 0; k < 8; k++) p2r[k] = pk2(ps[2 * k], ps[2 * k + 1]);
            }
            const float4* bp = (const float4*)&Bs[t][0];
            F4U2 B0, B1, B2, B3;
            B0.f4 = bp[0]; B1.f4 = bp[1]; B2.f4 = bp[2]; B3.f4 = bp[3];
            h2[0] = f2fma(h2[0], p2r[0], f2mul(dx2, B0.u2[0]));
            h2[1] = f2fma(h2[1], p2r[1], f2mul(dx2, B0.u2[1]));
            h2[2] = f2fma(h2[2], p2r[2], f2mul(dx2, B1.u2[0]));
            h2[3] = f2fma(h2[3], p2r[3], f2mul(dx2, B1.u2[1]));
            h2[4] = f2fma(h2[4], p2r[4], f2mul(dx2, B2.u2[0]));
            h2[5] = f2fma(h2[5], p2r[5], f2mul(dx2, B2.u2[1]));
            h2[6] = f2fma(h2[6], p2r[6], f2mul(dx2, B3.u2[0]));
            h2[7] = f2fma(h2[7], p2r[7], f2mul(dx2, B3.u2[1]));
        }
    }
    float* o = g_hF + (((size_t)b * CC + c) * DI + d) * DS;
    F4U2 o0, o1, o2, o3;
    o0.u2[0] = h2[0]; o0.u2[1] = h2[1];
    o1.u2[0] = h2[2]; o1.u2[1] = h2[3];
    o2.u2[0] = h2[4]; o2.u2[1] = h2[5];
    o3.u2[0] = h2[6]; o3.u2[1] = h2[7];
    *(float4*)(o + 0)  = o0.f4;
    *(float4*)(o + 4)  = o1.f4;
    *(float4*)(o + 8)  = o2.f4;
    *(float4*)(o + 12) = o3.f4;
    g_Ssum[((size_t)b * CC + c) * DI + d] = S;
}

// ---------------- K6b: propagate states across chunks -------------------------
__global__ __launch_bounds__(256) void k_scan2(void) {
    int idx = blockIdx.x * 256 + threadIdx.x;     // < 8192
    int b = idx >> 10;
    int d = idx & (DI - 1);
    int fast = g_fastA;
    float Areg[16];
    if (!fast) {
#pragma unroll
        for (int s = 0; s < 16; s++) Areg[s] = g_A[d * DS + s];
    }
    float H[16];
#pragma unroll
    for (int s = 0; s < 16; s++) H[s] = 0.f;
#pragma unroll 4
    for (int c = 0; c < CC; c++) {
        float* o = g_H + (((size_t)b * CC + c) * DI + d) * DS;
        *(float4*)(o + 0)  = make_float4(H[0], H[1], H[2], H[3]);
        *(float4*)(o + 4)  = make_float4(H[4], H[5], H[6], H[7]);
        *(float4*)(o + 8)  = make_float4(H[8], H[9], H[10], H[11]);
        *(float4*)(o + 12) = make_float4(H[12], H[13], H[14], H[15]);
        float S = g_Ssum[((size_t)b * CC + c) * DI + d];
        float p[16];
        if (fast) {
            float e1 = __expf(-S);
            POWTREE(p, e1)
        } else {
#pragma unroll
            for (int s = 0; s < 16; s++) p[s] = __expf(S * Areg[s]);
        }
        const float* f = g_hF + (((size_t)b * CC + c) * DI + d) * DS;
        float4 f0 = *(const float4*)(f + 0), f1 = *(const float4*)(f + 4);
        float4 f2 = *(const float4*)(f + 8), f3 = *(const float4*)(f + 12);
        H[0]  = fmaf(H[0],  p[0],  f0.x);  H[1]  = fmaf(H[1],  p[1],  f0.y);
        H[2]  = fmaf(H[2],  p[2],  f0.z);  H[3]  = fmaf(H[3],  p[3],  f0.w);
        H[4]  = fmaf(H[4],  p[4],  f1.x);  H[5]  = fmaf(H[5],  p[5],  f1.y);
        H[6]  = fmaf(H[6],  p[6],  f1.z);  H[7]  = fmaf(H[7],  p[7],  f1.w);
        H[8]  = fmaf(H[8],  p[8],  f2.x);  H[9]  = fmaf(H[9],  p[9],  f2.y);
        H[10] = fmaf(H[10], p[10], f2.z);  H[11] = fmaf(H[11], p[11], f2.w);
        H[12] = fmaf(H[12], p[12], f3.x);  H[13] = fmaf(H[13], p[13], f3.y);
        H[14] = fmaf(H[14], p[14], f3.z);  H[15] = fmaf(H[15], p[15], f3.w);
    }
}

// ---------------- K6c: full scan + gate + fused reduction ---------------------
__global__ __launch_bounds__(256) void k_scan3(const float* __restrict__ Dskip) {
    int blk = blockIdx.x;                // 1024 = b(8) x c(32) x dg(4)
    int b  = blk >> 7;
    int c  = (blk >> 2) & 31;
    int dg = blk & 3;
    int tid = threadIdx.x;
    int d  = dg * 256 + tid;
    int t0 = c * TT;
    int lane = tid & 31;
    int warp = tid >> 5;

    __shared__ float Bs[TT][DS];
    __shared__ float Cs[TT][DS];
    __shared__ float ash[TT], csh[TT];
    __shared__ float sred[8][TT];

    for (int i = tid; i < 2 * TT * DS; i += 256) {
        int half = i >> 10;
        int j = i & 1023;
        int s = j >> 6, t = j & 63;
        float v = half ? g_Ct[((size_t)b * DS + s) * LL + t0 + t]
                       : g_Bt[((size_t)b * DS + s) * LL + t0 + t];
        (half ? Cs : Bs)[t][s] = v;
    }
    if (tid < TT) {
        ash[tid] = g_a[b * LL + t0 + tid];
        csh[tid] = g_c[b * LL + t0 + tid];
    }

    const float4* dtp = (const float4*)(g_dtT + ((size_t)b * DI + d) * LL + t0);
    const float4* xcp = (const float4*)(g_xc  + ((size_t)b * DI + d) * LL + t0);
    int fast = g_fastA;
    float Areg[16];
    if (!fast) {
#pragma unroll
        for (int s = 0; s < 16; s++) Areg[s] = g_A[d * DS + s];
    }
    float p1z = g_p1[DI + d], p2z = g_p2[DI + d], p3z = g_p3[DI + d];
    float we = g_weff[d];
    float Dd = Dskip[d];
    u64 h2[8];
    {
        const float* Hp = g_H + (((size_t)b * CC + c) * DI + d) * DS;
        F4U2 H0, H1, H2, H3;
        H0.f4 = *(const float4*)(Hp + 0);
        H1.f4 = *(const float4*)(Hp + 4);
        H2.f4 = *(const float4*)(Hp + 8);
        H3.f4 = *(const float4*)(Hp + 12);
        h2[0] = H0.u2[0]; h2[1] = H0.u2[1];
        h2[2] = H1.u2[0]; h2[3] = H1.u2[1];
        h2[4] = H2.u2[0]; h2[5] = H2.u2[1];
        h2[6] = H3.u2[0]; h2[7] = H3.u2[1];
    }
    __syncthreads();

#pragma unroll 2
    for (int q = 0; q < TT / 4; q++) {
        float4 dtv = dtp[q], xcv = xcp[q];
#pragma unroll
        for (int u = 0; u < 4; u++) {
            float dtc = (u == 0) ? dtv.x : (u == 1) ? dtv.y : (u == 2) ? dtv.z : dtv.w;
            float xcc = (u == 0) ? xcv.x : (u == 1) ? xcv.y : (u == 2) ? xcv.z : xcv.w;
            int tt = q * 4 + u;
            float dx = dtc * xcc;
            u64 dx2 = pk2(dx, dx);
            u64 p2r[8];
            if (fast) {
                pow16(__expf(-dtc), p2r);
            } else {
                float ps[16];
#pragma unroll
                for (int s = 0; s < 16; s++) ps[s] = __expf(dtc * Areg[s]);
#pragma unroll
                for (int k = 0; k < 8; k++) p2r[k] = pk2(ps[2 * k], ps[2 * k + 1]);
            }
            const float4* bp = (const float4*)&Bs[tt][0];
            const float4* cp = (const float4*)&Cs[tt][0];
            F4U2 B0, B1, B2, B3, C0, C1, C2, C3;
            B0.f4 = bp[0]; B1.f4 = bp[1]; B2.f4 = bp[2]; B3.f4 = bp[3];
            C0.f4 = cp[0]; C1.f4 = cp[1]; C2.f4 = cp[2]; C3.f4 = cp[3];
            h2[0] = f2fma(h2[0], p2r[0], f2mul(dx2, B0.u2[0]));
            h2[1] = f2fma(h2[1], p2r[1], f2mul(dx2, B0.u2[1]));
            h2[2] = f2fma(h2[2], p2r[2], f2mul(dx2, B1.u2[0]));
            h2[3] = f2fma(h2[3], p2r[3], f2mul(dx2, B1.u2[1]));
            h2[4] = f2fma(h2[4], p2r[4], f2mul(dx2, B2.u2[0]));
            h2[5] = f2fma(h2[5], p2r[5], f2mul(dx2, B2.u2[1]));
            h2[6] = f2fma(h2[6], p2r[6], f2mul(dx2, B3.u2[0]));
            h2[7] = f2fma(h2[7], p2r[7], f2mul(dx2, B3.u2[1]));
            u64 y2 = f2mul(h2[0], C0.u2[0]);
            y2 = f2fma(h2[1], C0.u2[1], y2);
            y2 = f2fma(h2[2], C1.u2[0], y2);
            y2 = f2fma(h2[3], C1.u2[1], y2);
            y2 = f2fma(h2[4], C2.u2[0], y2);
            y2 = f2fma(h2[5], C2.u2[1], y2);
            y2 = f2fma(h2[6], C3.u2[0], y2);
            y2 = f2fma(h2[7], C3.u2[1], y2);
            float ylo, yhi;
            upk2(y2, ylo, yhi);
            float y = ylo + yhi;
            float z  = fmaf(ash[tt], p1z, fmaf(csh[tt], p2z, p3z));
            float zs = __fdividef(z, 1.0f + __expf(-z)) * we;
            float outv = fmaf(Dd, xcc, y) * zs;
#pragma unroll
            for (int o = 16; o > 0; o >>= 1)
                outv += __shfl_xor_sync(0xffffffffu, outv, o);
            if (lane == 0) sred[warp][tt] = outv;
        }
    }
    __syncthreads();
    if (tid < TT) {
        float s = 0.f;
#pragma unroll
        for (int w = 0; w < 8; w++) s += sred[w][tid];
        g_red[dg * (BB * LL) + b * LL + t0 + tid] = s;
    }
}

// ---------------- K7: combine 4 d-group partials + residual -------------------
__global__ __launch_bounds__(256) void k_fin2(const float* __restrict__ x,
                                              const float* __restrict__ bout,
                                              float* __restrict__ out) {
    int row = blockIdx.x * 256 + threadIdx.x;   // < 16384
    float s = g_red[row] + g_red[BB * LL + row] + g_red[2 * BB * LL + row] +
              g_red[3 * BB * LL + row];
    out[row] = s + bout[0] + x[row];
}

// ---------------- launch ------------------------------------------------------
extern "C" void kernel_launch(void* const* d_in, const int* in_sizes, int n_in,
                              void* d_out, int out_size) {
    const float* x      = (const float*)d_in[0];
    const float* W_in1  = (const float*)d_in[1];
    const float* b_in1  = (const float*)d_in[2];
    const float* ln_g   = (const float*)d_in[3];
    const float* ln_b   = (const float*)d_in[4];
    const float* W_xz   = (const float*)d_in[5];
    const float* conv_w = (const float*)d_in[6];
    const float* conv_b = (const float*)d_in[7];
    const float* W_xp   = (const float*)d_in[8];
    const float* W_dt   = (const float*)d_in[9];
    const float* b_dt   = (const float*)d_in[10];
    const float* A_log  = (const float*)d_in[11];
    const float* D_skip = (const float*)d_in[12];
    const float* W_om   = (const float*)d_in[13];
    const float* W_out  = (const float*)d_in[14];
    const float* b_out  = (const float*)d_in[15];
    float* out = (float*)d_out;

    k_stats<<<1, 512>>>(W_in1, b_in1);
    k_prep<<<140, 256>>>(W_in1, b_in1, ln_g, ln_b, W_xz, W_om, W_out, A_log, x);
    k_xc<<<1024, 256>>>(conv_w, conv_b);
    k_proj<<<256, 256>>>(W_xp);
    k_dt<<<1024, 256>>>(W_dt, b_dt);
    k_scan1<<<1024, 256>>>();
    k_scan2<<<32, 256>>>();
    k_scan3<<<1024, 256>>>(D_skip);
    k_fin2<<<64, 256>>>(x, b_out, out);
}